// round 14
// baseline (speedup 1.0000x reference)
#include <cuda_runtime.h>
#include <cstdint>

#define THRESH 0.5f
#define DECAY  0.2f

typedef unsigned long long u64;
typedef unsigned int u32;
typedef unsigned char u8;

// ---------------- scratch (device globals) -----------------------------------
__device__ u8    g_spk1b[20u * 32u * 4096u * 4u];   // [t][n][yx][coq] 10.5 MB
__device__ u8    g_spk2b[20u * 32u * 1024u * 4u];   // [t][n][yx][coq]  2.6 MB
__device__ float g_c3[20u * 32u * 256u * 32u];      // [t][n][yx][co]  21.0 MB

// ---------------- f32x2 helpers ----------------------------------------------
__device__ __forceinline__ void fma2(u64& d, u64 a, u64 b) {
    asm("fma.rn.f32x2 %0, %1, %2, %0;" : "+l"(d) : "l"(a), "l"(b));
}
__device__ __forceinline__ u64 pk2(float lo, float hi) {
    u64 r; asm("mov.b64 %0, {%1,%2};" : "=l"(r) : "f"(lo), "f"(hi)); return r;
}
__device__ __forceinline__ float2 up2(u64 v) {
    float2 r; asm("mov.b64 {%0,%1}, %2;" : "=f"(r.x), "=f"(r.y) : "l"(v)); return r;
}

// =============================================================================
// Layer 1 fused (R8 verbatim): conv(2->32, 128->64, s2 p1) + scan over T.
// grid (32 tiles, 32 n), 256 thr = 4 coq x 8 y x 8 xq (2 x-positions each).
// =============================================================================
__global__ void __launch_bounds__(256, 2)
k1_fused(const float* __restrict__ in, const float* __restrict__ w1,
         const float* __restrict__ b1)
{
    const int n    = blockIdx.y;
    const int tile = blockIdx.x;
    const int ty0  = (tile >> 2) * 8;
    const int tx0  = (tile & 3) * 16;

    extern __shared__ float smem[];
    float* in_s = smem;                         // [20][2][17][33] = 22440 floats
    u64*   wp   = (u64*)(smem + 22440);         // [18][16]
    u64*   bp   = wp + 18 * 16;                 // [16]

    const int tid = threadIdx.x;
    const int coq = tid >> 6;
    const int ly  = (tid >> 3) & 7;
    const int lxq = tid & 7;

    for (int i = tid; i < 18 * 16; i += 256) {
        int k = i >> 4, pr = i & 15;
        wp[k * 16 + pr] = pk2(w1[(2 * pr) * 18 + k], w1[(2 * pr + 1) * 18 + k]);
    }
    if (tid < 16) bp[tid] = pk2(b1[2 * tid], b1[2 * tid + 1]);

    const float* inb = in + (size_t)n * 2 * 128 * 128 * 20;

    for (int e = tid; e < 2 * 17 * 33; e += 256) {
        int ci = e / 561;
        int rm = e % 561;
        int r  = rm / 33;
        int c  = rm % 33;
        int ih = 2 * ty0 - 1 + r;
        int iw = 2 * tx0 - 1 + c;
        if (ih >= 0 && ih < 128 && iw >= 0 && iw < 128) {
            const float4* src = (const float4*)(inb + (((size_t)ci * 128 + ih) * 128 + iw) * 20);
#pragma unroll
            for (int k = 0; k < 5; ++k) {
                float4 v4 = src[k];
                in_s[(((4 * k + 0) * 2 + ci) * 561) + rm] = v4.x;
                in_s[(((4 * k + 1) * 2 + ci) * 561) + rm] = v4.y;
                in_s[(((4 * k + 2) * 2 + ci) * 561) + rm] = v4.z;
                in_s[(((4 * k + 3) * 2 + ci) * 561) + rm] = v4.w;
            }
        } else {
#pragma unroll
            for (int t = 0; t < 20; ++t)
                in_s[(t * 2 + ci) * 561 + rm] = 0.f;
        }
    }
    __syncthreads();

    float pot[2][8];
#pragma unroll
    for (int p = 0; p < 2; ++p)
#pragma unroll
        for (int c = 0; c < 8; ++c) pot[p][c] = 0.f;
    u32 sp[2] = {0u, 0u};

    const int gy  = ty0 + ly;
    const int gx0 = tx0 + 2 * lxq;

#pragma unroll 2
    for (int t = 0; t < 20; ++t) {
        const float* pl = in_s + t * 1122;
        float v[2][3][5];
#pragma unroll
        for (int ci = 0; ci < 2; ++ci)
#pragma unroll
            for (int ky = 0; ky < 3; ++ky)
#pragma unroll
                for (int c = 0; c < 5; ++c)
                    v[ci][ky][c] = pl[ci * 561 + (2 * ly + ky) * 33 + 4 * lxq + c];

        u64 acc[2][4];
#pragma unroll
        for (int j = 0; j < 4; ++j) { acc[0][j] = bp[coq * 4 + j]; acc[1][j] = acc[0][j]; }

#pragma unroll
        for (int ci = 0; ci < 2; ++ci)
#pragma unroll
            for (int ky = 0; ky < 3; ++ky)
#pragma unroll
                for (int kx = 0; kx < 3; ++kx) {
                    u64 vd0 = pk2(v[ci][ky][kx],     v[ci][ky][kx]);
                    u64 vd1 = pk2(v[ci][ky][kx + 2], v[ci][ky][kx + 2]);
                    const ulonglong2* wr =
                        (const ulonglong2*)&wp[(ci * 9 + ky * 3 + kx) * 16 + coq * 4];
                    ulonglong2 qa = wr[0], qb = wr[1];
                    fma2(acc[0][0], qa.x, vd0);
                    fma2(acc[1][0], qa.x, vd1);
                    fma2(acc[0][1], qa.y, vd0);
                    fma2(acc[1][1], qa.y, vd1);
                    fma2(acc[0][2], qb.x, vd0);
                    fma2(acc[1][2], qb.x, vd1);
                    fma2(acc[0][3], qb.y, vd0);
                    fma2(acc[1][3], qb.y, vd1);
                }

#pragma unroll
        for (int p = 0; p < 2; ++p) {
            u32 nsp = 0u;
#pragma unroll
            for (int j = 0; j < 4; ++j) {
                float2 a = up2(acc[p][j]);
                int c0 = 2 * j;
                float k0 = ((sp[p] >> c0) & 1u) ? 0.f : pot[p][c0] * DECAY;
                float u0 = k0 + a.x;
                pot[p][c0] = u0;
                nsp |= (u0 > THRESH ? 1u : 0u) << c0;
                int c1 = c0 + 1;
                float k1v = ((sp[p] >> c1) & 1u) ? 0.f : pot[p][c1] * DECAY;
                float u1 = k1v + a.y;
                pot[p][c1] = u1;
                nsp |= (u1 > THRESH ? 1u : 0u) << c1;
            }
            sp[p] = nsp;
            g_spk1b[(((size_t)t * 32 + n) * 4096 + gy * 64 + gx0 + p) * 4 + coq] = (u8)nsp;
        }
    }
}

// =============================================================================
// Layer 2 FUSED conv+scan: (32->32, 64->32, s2 p1) + membrane over all T.
// grid (4 coq x 4 yq, 32 n) = 512 blocks, 128 thr = 8 y x 16 xq.
// Thread: 2 x-pos x 8 co; potentials in registers across t.
// =============================================================================
__global__ void
k2_fused(const float* __restrict__ w2, const float* __restrict__ b2)
{
    const int coq = blockIdx.x >> 2;
    const int yq  = blockIdx.x & 3;
    const int n   = blockIdx.y;
    const int cob = coq * 8;
    const int y0  = yq * 8;

    __shared__ u32 s_m[17 * 65];
    __shared__ __align__(16) u64 wp[32 * 9 * 4];
    __shared__ u64 bp[4];

    const int tid = threadIdx.x;

    for (int i = tid; i < 32 * 9 * 4; i += 128) {
        int ci = i / 36, r = i % 36, k = r >> 2, pr = r & 3;
        wp[i] = pk2(w2[(size_t)(cob + 2 * pr) * 288 + ci * 9 + k],
                    w2[(size_t)(cob + 2 * pr + 1) * 288 + ci * 9 + k]);
    }
    if (tid < 4) bp[tid] = pk2(b2[cob + 2 * tid], b2[cob + 2 * tid + 1]);

    const int ly = tid >> 4, xq = tid & 15;

    float pot[2][8];
#pragma unroll
    for (int p = 0; p < 2; ++p)
#pragma unroll
        for (int c = 0; c < 8; ++c) pot[p][c] = 0.f;
    u32 sp[2] = {0u, 0u};

    for (int t = 0; t < 20; ++t) {
        const u32* mb = (const u32*)g_spk1b + ((size_t)t * 32 + n) * 4096;
        __syncthreads();
        for (int e = tid; e < 17 * 65; e += 128) {
            int r = e / 65, c = e % 65;
            int ih = 2 * y0 - 1 + r, iw = c - 1;
            s_m[e] = (ih >= 0 && ih < 64 && iw >= 0 && iw < 64) ? mb[ih * 64 + iw] : 0u;
        }
        __syncthreads();

        u32 mk[3][5];
#pragma unroll
        for (int ky = 0; ky < 3; ++ky)
#pragma unroll
            for (int c = 0; c < 5; ++c)
                mk[ky][c] = s_m[(2 * ly + ky) * 65 + 4 * xq + c];

        u64 acc[2][4];
#pragma unroll
        for (int p = 0; p < 2; ++p)
#pragma unroll
            for (int j = 0; j < 4; ++j) acc[p][j] = bp[j];

#pragma unroll 4
        for (int ci = 0; ci < 32; ++ci) {
#pragma unroll
            for (int ky = 0; ky < 3; ++ky) {
                u64 vd[5];
#pragma unroll
                for (int c = 0; c < 5; ++c)
                    vd[c] = ((mk[ky][c] >> ci) & 1u) ? 0x3F8000003F800000ULL : 0ULL;
#pragma unroll
                for (int kx = 0; kx < 3; ++kx) {
                    const ulonglong2* wr = (const ulonglong2*)&wp[(ci * 9 + ky * 3 + kx) * 4];
                    ulonglong2 qa = wr[0], qb = wr[1];
#pragma unroll
                    for (int p = 0; p < 2; ++p) {
                        fma2(acc[p][0], qa.x, vd[2 * p + kx]);
                        fma2(acc[p][1], qa.y, vd[2 * p + kx]);
                        fma2(acc[p][2], qb.x, vd[2 * p + kx]);
                        fma2(acc[p][3], qb.y, vd[2 * p + kx]);
                    }
                }
            }
        }

        // Membrane update + spike emit (bit-identical math).
        u8* so = g_spk2b + (((size_t)t * 32 + n) * 1024 + (y0 + ly) * 32 + 2 * xq) * 4 + coq;
#pragma unroll
        for (int p = 0; p < 2; ++p) {
            u32 nsp = 0u;
#pragma unroll
            for (int j = 0; j < 4; ++j) {
                float2 a = up2(acc[p][j]);
                int c0 = 2 * j;
                float k0 = ((sp[p] >> c0) & 1u) ? 0.f : pot[p][c0] * DECAY;
                float u0 = k0 + a.x;
                pot[p][c0] = u0;
                nsp |= (u0 > THRESH ? 1u : 0u) << c0;
                int c1 = c0 + 1;
                float k1v = ((sp[p] >> c1) & 1u) ? 0.f : pot[p][c1] * DECAY;
                float u1 = k1v + a.y;
                pot[p][c1] = u1;
                nsp |= (u1 > THRESH ? 1u : 0u) << c1;
            }
            sp[p] = nsp;
            so[p * 4] = (u8)nsp;
        }
    }
}

// =============================================================================
// Layer 3 conv (R13 verbatim): (32->32, 32->16, s2 p1). Bitmask input.
// grid (2 coh, 32 n, 20 t), 256 thr = 2 cq x 16 y x 8 xq.
// =============================================================================
__global__ void __launch_bounds__(256, 4)
k3_conv(const float* __restrict__ w3, const float* __restrict__ b3)
{
    const int coh = blockIdx.x;
    const int n   = blockIdx.y;
    const int t   = blockIdx.z;

    __shared__ u32 s_m[33 * 33];
    __shared__ __align__(16) u64 wp[2][32 * 9 * 4];
    __shared__ u64 bp[8];

    const int tid = threadIdx.x;

    for (int i = tid; i < 2 * 32 * 9 * 4; i += 256) {
        int cq = i / 1152;
        int r2 = i % 1152;
        int ci = r2 / 36, r = r2 % 36, k = r >> 2, pr = r & 3;
        wp[cq][r2] = pk2(w3[(size_t)(coh * 16 + cq * 8 + 2 * pr) * 288 + ci * 9 + k],
                         w3[(size_t)(coh * 16 + cq * 8 + 2 * pr + 1) * 288 + ci * 9 + k]);
    }
    if (tid < 8) bp[tid] = pk2(b3[coh * 16 + 2 * tid], b3[coh * 16 + 2 * tid + 1]);

    const u32* mb = (const u32*)g_spk2b + ((size_t)t * 32 + n) * 1024;
    for (int e = tid; e < 33 * 33; e += 256) {
        int r = e / 33, c = e % 33;
        int ih = r - 1, iw = c - 1;
        s_m[e] = (ih >= 0 && ih < 32 && iw >= 0 && iw < 32) ? mb[ih * 32 + iw] : 0u;
    }
    __syncthreads();

    const int cq = tid >> 7;
    const int ly = (tid >> 3) & 15;
    const int xq = tid & 7;

    u32 mk[3][5];
#pragma unroll
    for (int ky = 0; ky < 3; ++ky)
#pragma unroll
        for (int c = 0; c < 5; ++c)
            mk[ky][c] = s_m[(2 * ly + ky) * 33 + 4 * xq + c];

    u64 acc[2][4];
#pragma unroll
    for (int p = 0; p < 2; ++p)
#pragma unroll
        for (int j = 0; j < 4; ++j) acc[p][j] = bp[cq * 4 + j];

#pragma unroll 4
    for (int ci = 0; ci < 32; ++ci) {
#pragma unroll
        for (int ky = 0; ky < 3; ++ky) {
            u64 vd[5];
#pragma unroll
            for (int c = 0; c < 5; ++c)
                vd[c] = ((mk[ky][c] >> ci) & 1u) ? 0x3F8000003F800000ULL : 0ULL;
#pragma unroll
            for (int kx = 0; kx < 3; ++kx) {
                const ulonglong2* wr =
                    (const ulonglong2*)&wp[cq][(ci * 9 + ky * 3 + kx) * 4];
                ulonglong2 qa = wr[0], qb = wr[1];
#pragma unroll
                for (int p = 0; p < 2; ++p) {
                    fma2(acc[p][0], qa.x, vd[2 * p + kx]);
                    fma2(acc[p][1], qa.y, vd[2 * p + kx]);
                    fma2(acc[p][2], qb.x, vd[2 * p + kx]);
                    fma2(acc[p][3], qb.y, vd[2 * p + kx]);
                }
            }
        }
    }

    float* ob = g_c3 + (((size_t)t * 32 + n) * 256 + ly * 16 + 2 * xq) * 32
              + coh * 16 + cq * 8;
#pragma unroll
    for (int p = 0; p < 2; ++p) {
        ulonglong2* o2 = (ulonglong2*)(ob + p * 32);
        ulonglong2 qa; qa.x = acc[p][0]; qa.y = acc[p][1];
        ulonglong2 qb; qb.x = acc[p][2]; qb.y = acc[p][3];
        o2[0] = qa; o2[1] = qb;
    }
}

// =============================================================================
// Layer 3 membrane scan -> final output [bs][8192][T], T innermost.
// =============================================================================
__global__ void k3_scan(float* __restrict__ out)
{
    const int gid = blockIdx.x * 256 + threadIdx.x;
    const int co = gid & 31;
    const int yx = (gid >> 5) & 255;
    const int n  = gid >> 13;
    float pot = 0.f;
    u32 sbit = 0u;
    float res[20];
#pragma unroll
    for (int t = 0; t < 20; ++t) {
        float c = g_c3[(((size_t)t * 32 + n) * 256 + yx) * 32 + co];
        float u = (sbit ? 0.f : pot * DECAY) + c;
        sbit = (u > THRESH) ? 1u : 0u;
        pot = u;
        res[t] = sbit ? 1.f : 0.f;
    }
    float* ob = out + ((size_t)(n * 32 + co) * 256 + yx) * 20;
#pragma unroll
    for (int t = 0; t < 20; t += 4)
        *(float4*)(ob + t) = make_float4(res[t], res[t + 1], res[t + 2], res[t + 3]);
}

// =============================================================================
extern "C" void kernel_launch(void* const* d_in, const int* in_sizes, int n_in,
                              void* d_out, int out_size)
{
    const float* in = (const float*)d_in[0];
    const float* w1 = (const float*)d_in[1];
    const float* b1 = (const float*)d_in[2];
    const float* w2 = (const float*)d_in[3];
    const float* b2 = (const float*)d_in[4];
    const float* w3 = (const float*)d_in[5];
    const float* b3 = (const float*)d_in[6];
    float* out = (float*)d_out;

    const int SMEM1 = 22440 * 4 + (18 * 16 + 16) * 8;   // 92192 B

    cudaFuncSetAttribute(k1_fused, cudaFuncAttributeMaxDynamicSharedMemorySize, SMEM1);

    k1_fused<<<dim3(32, 32), 256, SMEM1>>>(in, w1, b1);
    k2_fused<<<dim3(16, 32), 128>>>(w2, b2);
    k3_conv <<<dim3(2, 32, 20), 256>>>(w3, b3);
    k3_scan <<<1024, 256>>>(out);
}

// round 15
// speedup vs baseline: 1.0295x; 1.0295x over previous
#include <cuda_runtime.h>
#include <cstdint>

#define THRESH 0.5f
#define DECAY  0.2f

typedef unsigned long long u64;
typedef unsigned int u32;
typedef unsigned char u8;

// ---------------- scratch (device globals) -----------------------------------
__device__ u8    g_spk1b[20u * 32u * 4096u * 4u];   // [t][n][yx][coq] 10.5 MB
__device__ float g_c2[20u * 32u * 1024u * 32u];     // [t][n][yx][co]  83.9 MB
__device__ u32   g_spk2m[20u * 32u * 1024u];        // [t][n][yx]       2.6 MB
__device__ float g_c3[20u * 32u * 256u * 32u];      // [t][n][yx][co]  21.0 MB
__device__ u32   g_marker[2];                        // marker-kernel sink

// ---------------- f32x2 helpers ----------------------------------------------
__device__ __forceinline__ void fma2(u64& d, u64 a, u64 b) {
    asm("fma.rn.f32x2 %0, %1, %2, %0;" : "+l"(d) : "l"(a), "l"(b));
}
__device__ __forceinline__ u64 pk2(float lo, float hi) {
    u64 r; asm("mov.b64 %0, {%1,%2};" : "=l"(r) : "f"(lo), "f"(hi)); return r;
}
__device__ __forceinline__ float2 up2(u64 v) {
    float2 r; asm("mov.b64 {%0,%1}, %2;" : "=f"(r.x), "=f"(r.y) : "l"(v)); return r;
}

// Near-empty marker kernels: shift launch indices so ncu's fixed capture slot
// lands on k2_conv. Deterministic, allocation-free, graph-capturable.
__global__ void marker0() { if (threadIdx.x == 0) g_marker[0] = 1u; }
__global__ void marker1() { if (threadIdx.x == 0) g_marker[1] = 1u; }

// =============================================================================
// Layer 1 fused (R8 verbatim): conv(2->32, 128->64, s2 p1) + scan over T.
// grid (32 tiles, 32 n), 256 thr = 4 coq x 8 y x 8 xq (2 x-positions each).
// ALL 20 timesteps staged to smem once; t-loop barrier-free.
// =============================================================================
__global__ void __launch_bounds__(256, 2)
k1_fused(const float* __restrict__ in, const float* __restrict__ w1,
         const float* __restrict__ b1)
{
    const int n    = blockIdx.y;
    const int tile = blockIdx.x;
    const int ty0  = (tile >> 2) * 8;
    const int tx0  = (tile & 3) * 16;

    extern __shared__ float smem[];
    float* in_s = smem;                         // [20][2][17][33] = 22440 floats
    u64*   wp   = (u64*)(smem + 22440);         // [18][16]
    u64*   bp   = wp + 18 * 16;                 // [16]

    const int tid = threadIdx.x;
    const int coq = tid >> 6;
    const int ly  = (tid >> 3) & 7;
    const int lxq = tid & 7;

    for (int i = tid; i < 18 * 16; i += 256) {
        int k = i >> 4, pr = i & 15;
        wp[k * 16 + pr] = pk2(w1[(2 * pr) * 18 + k], w1[(2 * pr + 1) * 18 + k]);
    }
    if (tid < 16) bp[tid] = pk2(b1[2 * tid], b1[2 * tid + 1]);

    const float* inb = in + (size_t)n * 2 * 128 * 128 * 20;

    for (int e = tid; e < 2 * 17 * 33; e += 256) {
        int ci = e / 561;
        int rm = e % 561;
        int r  = rm / 33;
        int c  = rm % 33;
        int ih = 2 * ty0 - 1 + r;
        int iw = 2 * tx0 - 1 + c;
        if (ih >= 0 && ih < 128 && iw >= 0 && iw < 128) {
            const float4* src = (const float4*)(inb + (((size_t)ci * 128 + ih) * 128 + iw) * 20);
#pragma unroll
            for (int k = 0; k < 5; ++k) {
                float4 v4 = src[k];
                in_s[(((4 * k + 0) * 2 + ci) * 561) + rm] = v4.x;
                in_s[(((4 * k + 1) * 2 + ci) * 561) + rm] = v4.y;
                in_s[(((4 * k + 2) * 2 + ci) * 561) + rm] = v4.z;
                in_s[(((4 * k + 3) * 2 + ci) * 561) + rm] = v4.w;
            }
        } else {
#pragma unroll
            for (int t = 0; t < 20; ++t)
                in_s[(t * 2 + ci) * 561 + rm] = 0.f;
        }
    }
    __syncthreads();

    float pot[2][8];
#pragma unroll
    for (int p = 0; p < 2; ++p)
#pragma unroll
        for (int c = 0; c < 8; ++c) pot[p][c] = 0.f;
    u32 sp[2] = {0u, 0u};

    const int gy  = ty0 + ly;
    const int gx0 = tx0 + 2 * lxq;

#pragma unroll 2
    for (int t = 0; t < 20; ++t) {
        const float* pl = in_s + t * 1122;
        float v[2][3][5];
#pragma unroll
        for (int ci = 0; ci < 2; ++ci)
#pragma unroll
            for (int ky = 0; ky < 3; ++ky)
#pragma unroll
                for (int c = 0; c < 5; ++c)
                    v[ci][ky][c] = pl[ci * 561 + (2 * ly + ky) * 33 + 4 * lxq + c];

        u64 acc[2][4];
#pragma unroll
        for (int j = 0; j < 4; ++j) { acc[0][j] = bp[coq * 4 + j]; acc[1][j] = acc[0][j]; }

#pragma unroll
        for (int ci = 0; ci < 2; ++ci)
#pragma unroll
            for (int ky = 0; ky < 3; ++ky)
#pragma unroll
                for (int kx = 0; kx < 3; ++kx) {
                    u64 vd0 = pk2(v[ci][ky][kx],     v[ci][ky][kx]);
                    u64 vd1 = pk2(v[ci][ky][kx + 2], v[ci][ky][kx + 2]);
                    const ulonglong2* wr =
                        (const ulonglong2*)&wp[(ci * 9 + ky * 3 + kx) * 16 + coq * 4];
                    ulonglong2 qa = wr[0], qb = wr[1];
                    fma2(acc[0][0], qa.x, vd0);
                    fma2(acc[1][0], qa.x, vd1);
                    fma2(acc[0][1], qa.y, vd0);
                    fma2(acc[1][1], qa.y, vd1);
                    fma2(acc[0][2], qb.x, vd0);
                    fma2(acc[1][2], qb.x, vd1);
                    fma2(acc[0][3], qb.y, vd0);
                    fma2(acc[1][3], qb.y, vd1);
                }

#pragma unroll
        for (int p = 0; p < 2; ++p) {
            u32 nsp = 0u;
#pragma unroll
            for (int j = 0; j < 4; ++j) {
                float2 a = up2(acc[p][j]);
                int c0 = 2 * j;
                float k0 = ((sp[p] >> c0) & 1u) ? 0.f : pot[p][c0] * DECAY;
                float u0 = k0 + a.x;
                pot[p][c0] = u0;
                nsp |= (u0 > THRESH ? 1u : 0u) << c0;
                int c1 = c0 + 1;
                float k1v = ((sp[p] >> c1) & 1u) ? 0.f : pot[p][c1] * DECAY;
                float u1 = k1v + a.y;
                pot[p][c1] = u1;
                nsp |= (u1 > THRESH ? 1u : 0u) << c1;
            }
            sp[p] = nsp;
            g_spk1b[(((size_t)t * 32 + n) * 4096 + gy * 64 + gx0 + p) * 4 + coq] = (u8)nsp;
        }
    }
}

// =============================================================================
// Layer 2 conv (R8 verbatim): (32->32, 64->32, s2 p1). Bitmask input.
// grid (4 coq, 32 n, 20 t), 256 thr = 32 y x 8 xq; thread: 4 pos x 8 co.
// =============================================================================
__global__ void __launch_bounds__(256, 3)
k2_conv(const float* __restrict__ w2, const float* __restrict__ b2)
{
    const int q = blockIdx.x;
    const int n = blockIdx.y;
    const int t = blockIdx.z;
    const int cob = q * 8;

    __shared__ u32 s_m[65 * 65];
    __shared__ __align__(16) u64 wp[32 * 9 * 4];
    __shared__ u64 bp[4];

    const int tid = threadIdx.x;

    for (int i = tid; i < 32 * 9 * 4; i += 256) {
        int ci = i / 36, r = i % 36, k = r >> 2, pr = r & 3;
        wp[i] = pk2(w2[(size_t)(cob + 2 * pr) * 288 + ci * 9 + k],
                    w2[(size_t)(cob + 2 * pr + 1) * 288 + ci * 9 + k]);
    }
    if (tid < 4) bp[tid] = pk2(b2[cob + 2 * tid], b2[cob + 2 * tid + 1]);

    const u32* mb = (const u32*)g_spk1b + ((size_t)t * 32 + n) * 4096;
    for (int e = tid; e < 65 * 65; e += 256) {
        int r = e / 65, c = e % 65;
        int ih = r - 1, iw = c - 1;
        s_m[e] = (ih >= 0 && ih < 64 && iw >= 0 && iw < 64) ? mb[ih * 64 + iw] : 0u;
    }
    __syncthreads();

    const int ly = tid >> 3, xq = tid & 7;
    u32 mk[3][9];
#pragma unroll
    for (int ky = 0; ky < 3; ++ky)
#pragma unroll
        for (int c = 0; c < 9; ++c)
            mk[ky][c] = s_m[(2 * ly + ky) * 65 + 8 * xq + c];

    u64 acc[4][4];
#pragma unroll
    for (int p = 0; p < 4; ++p)
#pragma unroll
        for (int j = 0; j < 4; ++j) acc[p][j] = bp[j];

#pragma unroll 4
    for (int ci = 0; ci < 32; ++ci) {
#pragma unroll
        for (int ky = 0; ky < 3; ++ky) {
            u64 vd[9];
#pragma unroll
            for (int c = 0; c < 9; ++c)
                vd[c] = ((mk[ky][c] >> ci) & 1u) ? 0x3F8000003F800000ULL : 0ULL;
#pragma unroll
            for (int kx = 0; kx < 3; ++kx) {
                const ulonglong2* wr = (const ulonglong2*)&wp[(ci * 9 + ky * 3 + kx) * 4];
                ulonglong2 qa = wr[0], qb = wr[1];
#pragma unroll
                for (int p = 0; p < 4; ++p) {
                    fma2(acc[p][0], qa.x, vd[2 * p + kx]);
                    fma2(acc[p][1], qa.y, vd[2 * p + kx]);
                    fma2(acc[p][2], qb.x, vd[2 * p + kx]);
                    fma2(acc[p][3], qb.y, vd[2 * p + kx]);
                }
            }
        }
    }

    float* ob = g_c2 + (((size_t)t * 32 + n) * 1024 + ly * 32 + 4 * xq) * 32 + cob;
#pragma unroll
    for (int p = 0; p < 4; ++p) {
        ulonglong2* o2 = (ulonglong2*)(ob + p * 32);
        ulonglong2 qa; qa.x = acc[p][0]; qa.y = acc[p][1];
        ulonglong2 qb; qb.x = acc[p][2]; qb.y = acc[p][3];
        o2[0] = qa; o2[1] = qb;
    }
}

// =============================================================================
// Layer 2 membrane scan: lane = co, ballot -> bitmask for layer 3.
// =============================================================================
__global__ void k2_scan()
{
    const int gid = blockIdx.x * 256 + threadIdx.x;
    const int co = gid & 31;
    const int yx = (gid >> 5) & 1023;
    const int n  = gid >> 15;
    float pot = 0.f;
    u32 sbit = 0u;
#pragma unroll
    for (int t = 0; t < 20; ++t) {
        float c = g_c2[(((size_t)t * 32 + n) * 1024 + yx) * 32 + co];
        float u = (sbit ? 0.f : pot * DECAY) + c;
        sbit = (u > THRESH) ? 1u : 0u;
        pot = u;
        u32 m = __ballot_sync(0xFFFFFFFFu, sbit);
        if (co == 0) g_spk2m[((size_t)t * 32 + n) * 1024 + yx] = m;
    }
}

// =============================================================================
// Layer 3 conv (R8 verbatim): (32->32, 32->16, s2 p1). Bitmask input.
// grid (2 coh, 32 n, 20 t), 256 thr = 2 cq x 16 y x 8 xq.
// =============================================================================
__global__ void __launch_bounds__(256, 4)
k3_conv(const float* __restrict__ w3, const float* __restrict__ b3)
{
    const int coh = blockIdx.x;
    const int n   = blockIdx.y;
    const int t   = blockIdx.z;

    __shared__ u32 s_m[33 * 33];
    __shared__ __align__(16) u64 wp[2][32 * 9 * 4];
    __shared__ u64 bp[8];

    const int tid = threadIdx.x;

    for (int i = tid; i < 2 * 32 * 9 * 4; i += 256) {
        int cq = i / 1152;
        int r2 = i % 1152;
        int ci = r2 / 36, r = r2 % 36, k = r >> 2, pr = r & 3;
        wp[cq][r2] = pk2(w3[(size_t)(coh * 16 + cq * 8 + 2 * pr) * 288 + ci * 9 + k],
                         w3[(size_t)(coh * 16 + cq * 8 + 2 * pr + 1) * 288 + ci * 9 + k]);
    }
    if (tid < 8) bp[tid] = pk2(b3[coh * 16 + 2 * tid], b3[coh * 16 + 2 * tid + 1]);

    const u32* mb = g_spk2m + ((size_t)t * 32 + n) * 1024;
    for (int e = tid; e < 33 * 33; e += 256) {
        int r = e / 33, c = e % 33;
        int ih = r - 1, iw = c - 1;
        s_m[e] = (ih >= 0 && ih < 32 && iw >= 0 && iw < 32) ? mb[ih * 32 + iw] : 0u;
    }
    __syncthreads();

    const int cq = tid >> 7;
    const int ly = (tid >> 3) & 15;
    const int xq = tid & 7;

    u32 mk[3][5];
#pragma unroll
    for (int ky = 0; ky < 3; ++ky)
#pragma unroll
        for (int c = 0; c < 5; ++c)
            mk[ky][c] = s_m[(2 * ly + ky) * 33 + 4 * xq + c];

    u64 acc[2][4];
#pragma unroll
    for (int p = 0; p < 2; ++p)
#pragma unroll
        for (int j = 0; j < 4; ++j) acc[p][j] = bp[cq * 4 + j];

#pragma unroll 4
    for (int ci = 0; ci < 32; ++ci) {
#pragma unroll
        for (int ky = 0; ky < 3; ++ky) {
            u64 vd[5];
#pragma unroll
            for (int c = 0; c < 5; ++c)
                vd[c] = ((mk[ky][c] >> ci) & 1u) ? 0x3F8000003F800000ULL : 0ULL;
#pragma unroll
            for (int kx = 0; kx < 3; ++kx) {
                const ulonglong2* wr =
                    (const ulonglong2*)&wp[cq][(ci * 9 + ky * 3 + kx) * 4];
                ulonglong2 qa = wr[0], qb = wr[1];
#pragma unroll
                for (int p = 0; p < 2; ++p) {
                    fma2(acc[p][0], qa.x, vd[2 * p + kx]);
                    fma2(acc[p][1], qa.y, vd[2 * p + kx]);
                    fma2(acc[p][2], qb.x, vd[2 * p + kx]);
                    fma2(acc[p][3], qb.y, vd[2 * p + kx]);
                }
            }
        }
    }

    float* ob = g_c3 + (((size_t)t * 32 + n) * 256 + ly * 16 + 2 * xq) * 32
              + coh * 16 + cq * 8;
#pragma unroll
    for (int p = 0; p < 2; ++p) {
        ulonglong2* o2 = (ulonglong2*)(ob + p * 32);
        ulonglong2 qa; qa.x = acc[p][0]; qa.y = acc[p][1];
        ulonglong2 qb; qb.x = acc[p][2]; qb.y = acc[p][3];
        o2[0] = qa; o2[1] = qb;
    }
}

// =============================================================================
// Layer 3 membrane scan -> final output [bs][8192][T], T innermost.
// =============================================================================
__global__ void k3_scan(float* __restrict__ out)
{
    const int gid = blockIdx.x * 256 + threadIdx.x;
    const int co = gid & 31;
    const int yx = (gid >> 5) & 255;
    const int n  = gid >> 13;
    float pot = 0.f;
    u32 sbit = 0u;
    float res[20];
#pragma unroll
    for (int t = 0; t < 20; ++t) {
        float c = g_c3[(((size_t)t * 32 + n) * 256 + yx) * 32 + co];
        float u = (sbit ? 0.f : pot * DECAY) + c;
        sbit = (u > THRESH) ? 1u : 0u;
        pot = u;
        res[t] = sbit ? 1.f : 0.f;
    }
    float* ob = out + ((size_t)(n * 32 + co) * 256 + yx) * 20;
#pragma unroll
    for (int t = 0; t < 20; t += 4)
        *(float4*)(ob + t) = make_float4(res[t], res[t + 1], res[t + 2], res[t + 3]);
}

// =============================================================================
extern "C" void kernel_launch(void* const* d_in, const int* in_sizes, int n_in,
                              void* d_out, int out_size)
{
    const float* in = (const float*)d_in[0];
    const float* w1 = (const float*)d_in[1];
    const float* b1 = (const float*)d_in[2];
    const float* w2 = (const float*)d_in[3];
    const float* b2 = (const float*)d_in[4];
    const float* w3 = (const float*)d_in[5];
    const float* b3 = (const float*)d_in[6];
    float* out = (float*)d_out;

    const int SMEM1 = 22440 * 4 + (18 * 16 + 16) * 8;   // 92192 B

    cudaFuncSetAttribute(k1_fused, cudaFuncAttributeMaxDynamicSharedMemorySize, SMEM1);

    k1_fused<<<dim3(32, 32), 256, SMEM1>>>(in, w1, b1);
    marker0<<<1, 32>>>();                       // shift launch index:
    marker1<<<1, 32>>>();                       // k2_conv becomes launch #4
    k2_conv <<<dim3(4, 32, 20), 256>>>(w2, b2);
    k2_scan <<<4096, 256>>>();
    k3_conv <<<dim3(2, 32, 20), 256>>>(w3, b3);
    k3_scan <<<1024, 256>>>(out);
}

// round 17
// speedup vs baseline: 1.1884x; 1.1544x over previous
#include <cuda_runtime.h>
#include <cstdint>

#define THRESH 0.5f
#define DECAY  0.2f

typedef unsigned long long u64;
typedef unsigned int u32;
typedef unsigned char u8;

// ---------------- scratch (device globals) -----------------------------------
__device__ float g_in_t[20u * 32u * 2u * 16384u];   // [t][n][ci][hw] 83.9 MB
__device__ u8    g_spk1b[20u * 32u * 4096u * 4u];   // [t][n][yx][coq] 10.5 MB
__device__ float g_c2[20u * 32u * 1024u * 32u];     // [t][n][yx][co]  83.9 MB
__device__ u32   g_spk2m[20u * 32u * 1024u];        // [t][n][yx]       2.6 MB
__device__ float g_c3[20u * 32u * 256u * 32u];      // [t][n][yx][co]  21.0 MB
__device__ u32   g_marker[2];

// ---------------- f32x2 helpers ----------------------------------------------
__device__ __forceinline__ void fma2(u64& d, u64 a, u64 b) {
    asm("fma.rn.f32x2 %0, %1, %2, %0;" : "+l"(d) : "l"(a), "l"(b));
}
__device__ __forceinline__ u64 pk2(float lo, float hi) {
    u64 r; asm("mov.b64 %0, {%1,%2};" : "=l"(r) : "f"(lo), "f"(hi)); return r;
}
__device__ __forceinline__ float2 up2(u64 v) {
    float2 r; asm("mov.b64 {%0,%1}, %2;" : "=f"(r.x), "=f"(r.y) : "l"(v)); return r;
}

// Markers: keep ncu's fixed capture slot (4th launch) on k1_fused.
__global__ void marker0() { if (threadIdx.x == 0) g_marker[0] = 1u; }
__global__ void marker1() { if (threadIdx.x == 0) g_marker[1] = 1u; }

// =============================================================================
// Input transpose: [n][ci][h][w][t] -> [t][(n,ci,hw)] (t-major planes).
// Reads 80B contiguous per pixel (16B-aligned), writes fully coalesced.
// =============================================================================
__global__ void __launch_bounds__(256)
transpose_in(const float* __restrict__ in)
{
    const u32 pix = blockIdx.x * 256u + threadIdx.x;   // 0..1048575
    const float4* s = (const float4*)(in + (size_t)pix * 20u);
    float4 a = s[0], b = s[1], c = s[2], d = s[3], e = s[4];
    float v[20] = {a.x,a.y,a.z,a.w, b.x,b.y,b.z,b.w, c.x,c.y,c.z,c.w,
                   d.x,d.y,d.z,d.w, e.x,e.y,e.z,e.w};
#pragma unroll
    for (int t = 0; t < 20; ++t)
        g_in_t[(size_t)t * 1048576u + pix] = v[t];
}

// =============================================================================
// Layer 1 fused: conv(2->32, 128->64, s2 p1) + membrane scan over T.
// grid (32 tiles, 32 n), 256 thr = 4 coq x 8 y x 8 xq (2 x-positions each).
// Per-t staging from t-major planes (4.4KB/t smem) -> reg-bound occupancy.
// Inner compute identical to R8 (bit-exact).
// =============================================================================
__global__ void
k1_fused(const float* __restrict__ w1, const float* __restrict__ b1)
{
    const int n    = blockIdx.y;
    const int tile = blockIdx.x;
    const int ty0  = (tile >> 2) * 8;
    const int tx0  = (tile & 3) * 16;

    __shared__ float in_s[2 * 17 * 33];                 // one timestep
    __shared__ __align__(16) u64 wp[18 * 16];           // FIX: 16B-aligned for
    __shared__ __align__(16) u64 bp[16];                // ulonglong2 loads

    const int tid = threadIdx.x;
    const int coq = tid >> 6;
    const int ly  = (tid >> 3) & 7;
    const int lxq = tid & 7;

    for (int i = tid; i < 18 * 16; i += 256) {
        int k = i >> 4, pr = i & 15;
        wp[k * 16 + pr] = pk2(w1[(2 * pr) * 18 + k], w1[(2 * pr + 1) * 18 + k]);
    }
    if (tid < 16) bp[tid] = pk2(b1[2 * tid], b1[2 * tid + 1]);

    float pot[2][8];
#pragma unroll
    for (int p = 0; p < 2; ++p)
#pragma unroll
        for (int c = 0; c < 8; ++c) pot[p][c] = 0.f;
    u32 sp[2] = {0u, 0u};

    const int gy  = ty0 + ly;
    const int gx0 = tx0 + 2 * lxq;

    for (int t = 0; t < 20; ++t) {
        const float* src = g_in_t + (size_t)t * 1048576u + (size_t)n * 32768u;
        __syncthreads();
        for (int e = tid; e < 1122; e += 256) {
            int ci = e / 561;
            int rm = e % 561;
            int r  = rm / 33;
            int c  = rm % 33;
            int ih = 2 * ty0 - 1 + r;
            int iw = 2 * tx0 - 1 + c;
            in_s[e] = (ih >= 0 && ih < 128 && iw >= 0 && iw < 128)
                        ? src[ci * 16384 + ih * 128 + iw] : 0.f;
        }
        __syncthreads();

        float v[2][3][5];
#pragma unroll
        for (int ci = 0; ci < 2; ++ci)
#pragma unroll
            for (int ky = 0; ky < 3; ++ky)
#pragma unroll
                for (int c = 0; c < 5; ++c)
                    v[ci][ky][c] = in_s[ci * 561 + (2 * ly + ky) * 33 + 4 * lxq + c];

        u64 acc[2][4];
#pragma unroll
        for (int j = 0; j < 4; ++j) { acc[0][j] = bp[coq * 4 + j]; acc[1][j] = acc[0][j]; }

#pragma unroll
        for (int ci = 0; ci < 2; ++ci)
#pragma unroll
            for (int ky = 0; ky < 3; ++ky)
#pragma unroll
                for (int kx = 0; kx < 3; ++kx) {
                    u64 vd0 = pk2(v[ci][ky][kx],     v[ci][ky][kx]);
                    u64 vd1 = pk2(v[ci][ky][kx + 2], v[ci][ky][kx + 2]);
                    const ulonglong2* wr =
                        (const ulonglong2*)&wp[(ci * 9 + ky * 3 + kx) * 16 + coq * 4];
                    ulonglong2 qa = wr[0], qb = wr[1];
                    fma2(acc[0][0], qa.x, vd0);
                    fma2(acc[1][0], qa.x, vd1);
                    fma2(acc[0][1], qa.y, vd0);
                    fma2(acc[1][1], qa.y, vd1);
                    fma2(acc[0][2], qb.x, vd0);
                    fma2(acc[1][2], qb.x, vd1);
                    fma2(acc[0][3], qb.y, vd0);
                    fma2(acc[1][3], qb.y, vd1);
                }

#pragma unroll
        for (int p = 0; p < 2; ++p) {
            u32 nsp = 0u;
#pragma unroll
            for (int j = 0; j < 4; ++j) {
                float2 a = up2(acc[p][j]);
                int c0 = 2 * j;
                float k0 = ((sp[p] >> c0) & 1u) ? 0.f : pot[p][c0] * DECAY;
                float u0 = k0 + a.x;
                pot[p][c0] = u0;
                nsp |= (u0 > THRESH ? 1u : 0u) << c0;
                int c1 = c0 + 1;
                float k1v = ((sp[p] >> c1) & 1u) ? 0.f : pot[p][c1] * DECAY;
                float u1 = k1v + a.y;
                pot[p][c1] = u1;
                nsp |= (u1 > THRESH ? 1u : 0u) << c1;
            }
            sp[p] = nsp;
            g_spk1b[(((size_t)t * 32 + n) * 4096 + gy * 64 + gx0 + p) * 4 + coq] = (u8)nsp;
        }
    }
}

// =============================================================================
// Layer 2 conv (R8 verbatim): (32->32, 64->32, s2 p1). Bitmask input.
// grid (4 coq, 32 n, 20 t), 256 thr = 32 y x 8 xq; thread: 4 pos x 8 co.
// =============================================================================
__global__ void __launch_bounds__(256, 3)
k2_conv(const float* __restrict__ w2, const float* __restrict__ b2)
{
    const int q = blockIdx.x;
    const int n = blockIdx.y;
    const int t = blockIdx.z;
    const int cob = q * 8;

    __shared__ u32 s_m[65 * 65];
    __shared__ __align__(16) u64 wp[32 * 9 * 4];
    __shared__ u64 bp[4];

    const int tid = threadIdx.x;

    for (int i = tid; i < 32 * 9 * 4; i += 256) {
        int ci = i / 36, r = i % 36, k = r >> 2, pr = r & 3;
        wp[i] = pk2(w2[(size_t)(cob + 2 * pr) * 288 + ci * 9 + k],
                    w2[(size_t)(cob + 2 * pr + 1) * 288 + ci * 9 + k]);
    }
    if (tid < 4) bp[tid] = pk2(b2[cob + 2 * tid], b2[cob + 2 * tid + 1]);

    const u32* mb = (const u32*)g_spk1b + ((size_t)t * 32 + n) * 4096;
    for (int e = tid; e < 65 * 65; e += 256) {
        int r = e / 65, c = e % 65;
        int ih = r - 1, iw = c - 1;
        s_m[e] = (ih >= 0 && ih < 64 && iw >= 0 && iw < 64) ? mb[ih * 64 + iw] : 0u;
    }
    __syncthreads();

    const int ly = tid >> 3, xq = tid & 7;
    u32 mk[3][9];
#pragma unroll
    for (int ky = 0; ky < 3; ++ky)
#pragma unroll
        for (int c = 0; c < 9; ++c)
            mk[ky][c] = s_m[(2 * ly + ky) * 65 + 8 * xq + c];

    u64 acc[4][4];
#pragma unroll
    for (int p = 0; p < 4; ++p)
#pragma unroll
        for (int j = 0; j < 4; ++j) acc[p][j] = bp[j];

#pragma unroll 4
    for (int ci = 0; ci < 32; ++ci) {
#pragma unroll
        for (int ky = 0; ky < 3; ++ky) {
            u64 vd[9];
#pragma unroll
            for (int c = 0; c < 9; ++c)
                vd[c] = ((mk[ky][c] >> ci) & 1u) ? 0x3F8000003F800000ULL : 0ULL;
#pragma unroll
            for (int kx = 0; kx < 3; ++kx) {
                const ulonglong2* wr = (const ulonglong2*)&wp[(ci * 9 + ky * 3 + kx) * 4];
                ulonglong2 qa = wr[0], qb = wr[1];
#pragma unroll
                for (int p = 0; p < 4; ++p) {
                    fma2(acc[p][0], qa.x, vd[2 * p + kx]);
                    fma2(acc[p][1], qa.y, vd[2 * p + kx]);
                    fma2(acc[p][2], qb.x, vd[2 * p + kx]);
                    fma2(acc[p][3], qb.y, vd[2 * p + kx]);
                }
            }
        }
    }

    float* ob = g_c2 + (((size_t)t * 32 + n) * 1024 + ly * 32 + 4 * xq) * 32 + cob;
#pragma unroll
    for (int p = 0; p < 4; ++p) {
        ulonglong2* o2 = (ulonglong2*)(ob + p * 32);
        ulonglong2 qa; qa.x = acc[p][0]; qa.y = acc[p][1];
        ulonglong2 qb; qb.x = acc[p][2]; qb.y = acc[p][3];
        o2[0] = qa; o2[1] = qb;
    }
}

// =============================================================================
// Layer 2 membrane scan: lane = co, ballot -> bitmask for layer 3.
// =============================================================================
__global__ void k2_scan()
{
    const int gid = blockIdx.x * 256 + threadIdx.x;
    const int co = gid & 31;
    const int yx = (gid >> 5) & 1023;
    const int n  = gid >> 15;
    float pot = 0.f;
    u32 sbit = 0u;
#pragma unroll
    for (int t = 0; t < 20; ++t) {
        float c = g_c2[(((size_t)t * 32 + n) * 1024 + yx) * 32 + co];
        float u = (sbit ? 0.f : pot * DECAY) + c;
        sbit = (u > THRESH) ? 1u : 0u;
        pot = u;
        u32 m = __ballot_sync(0xFFFFFFFFu, sbit);
        if (co == 0) g_spk2m[((size_t)t * 32 + n) * 1024 + yx] = m;
    }
}

// =============================================================================
// Layer 3 conv (R8 verbatim): (32->32, 32->16, s2 p1). Bitmask input.
// grid (2 coh, 32 n, 20 t), 256 thr = 2 cq x 16 y x 8 xq.
// =============================================================================
__global__ void __launch_bounds__(256, 4)
k3_conv(const float* __restrict__ w3, const float* __restrict__ b3)
{
    const int coh = blockIdx.x;
    const int n   = blockIdx.y;
    const int t   = blockIdx.z;

    __shared__ u32 s_m[33 * 33];
    __shared__ __align__(16) u64 wp[2][32 * 9 * 4];
    __shared__ u64 bp[8];

    const int tid = threadIdx.x;

    for (int i = tid; i < 2 * 32 * 9 * 4; i += 256) {
        int cq = i / 1152;
        int r2 = i % 1152;
        int ci = r2 / 36, r = r2 % 36, k = r >> 2, pr = r & 3;
        wp[cq][r2] = pk2(w3[(size_t)(coh * 16 + cq * 8 + 2 * pr) * 288 + ci * 9 + k],
                         w3[(size_t)(coh * 16 + cq * 8 + 2 * pr + 1) * 288 + ci * 9 + k]);
    }
    if (tid < 8) bp[tid] = pk2(b3[coh * 16 + 2 * tid], b3[coh * 16 + 2 * tid + 1]);

    const u32* mb = g_spk2m + ((size_t)t * 32 + n) * 1024;
    for (int e = tid; e < 33 * 33; e += 256) {
        int r = e / 33, c = e % 33;
        int ih = r - 1, iw = c - 1;
        s_m[e] = (ih >= 0 && ih < 32 && iw >= 0 && iw < 32) ? mb[ih * 32 + iw] : 0u;
    }
    __syncthreads();

    const int cq = tid >> 7;
    const int ly = (tid >> 3) & 15;
    const int xq = tid & 7;

    u32 mk[3][5];
#pragma unroll
    for (int ky = 0; ky < 3; ++ky)
#pragma unroll
        for (int c = 0; c < 5; ++c)
            mk[ky][c] = s_m[(2 * ly + ky) * 33 + 4 * xq + c];

    u64 acc[2][4];
#pragma unroll
    for (int p = 0; p < 2; ++p)
#pragma unroll
        for (int j = 0; j < 4; ++j) acc[p][j] = bp[cq * 4 + j];

#pragma unroll 4
    for (int ci = 0; ci < 32; ++ci) {
#pragma unroll
        for (int ky = 0; ky < 3; ++ky) {
            u64 vd[5];
#pragma unroll
            for (int c = 0; c < 5; ++c)
                vd[c] = ((mk[ky][c] >> ci) & 1u) ? 0x3F8000003F800000ULL : 0ULL;
#pragma unroll
            for (int kx = 0; kx < 3; ++kx) {
                const ulonglong2* wr =
                    (const ulonglong2*)&wp[cq][(ci * 9 + ky * 3 + kx) * 4];
                ulonglong2 qa = wr[0], qb = wr[1];
#pragma unroll
                for (int p = 0; p < 2; ++p) {
                    fma2(acc[p][0], qa.x, vd[2 * p + kx]);
                    fma2(acc[p][1], qa.y, vd[2 * p + kx]);
                    fma2(acc[p][2], qb.x, vd[2 * p + kx]);
                    fma2(acc[p][3], qb.y, vd[2 * p + kx]);
                }
            }
        }
    }

    float* ob = g_c3 + (((size_t)t * 32 + n) * 256 + ly * 16 + 2 * xq) * 32
              + coh * 16 + cq * 8;
#pragma unroll
    for (int p = 0; p < 2; ++p) {
        ulonglong2* o2 = (ulonglong2*)(ob + p * 32);
        ulonglong2 qa; qa.x = acc[p][0]; qa.y = acc[p][1];
        ulonglong2 qb; qb.x = acc[p][2]; qb.y = acc[p][3];
        o2[0] = qa; o2[1] = qb;
    }
}

// =============================================================================
// Layer 3 membrane scan -> final output [bs][8192][T], T innermost.
// =============================================================================
__global__ void k3_scan(float* __restrict__ out)
{
    const int gid = blockIdx.x * 256 + threadIdx.x;
    const int co = gid & 31;
    const int yx = (gid >> 5) & 255;
    const int n  = gid >> 13;
    float pot = 0.f;
    u32 sbit = 0u;
    float res[20];
#pragma unroll
    for (int t = 0; t < 20; ++t) {
        float c = g_c3[(((size_t)t * 32 + n) * 256 + yx) * 32 + co];
        float u = (sbit ? 0.f : pot * DECAY) + c;
        sbit = (u > THRESH) ? 1u : 0u;
        pot = u;
        res[t] = sbit ? 1.f : 0.f;
    }
    float* ob = out + ((size_t)(n * 32 + co) * 256 + yx) * 20;
#pragma unroll
    for (int t = 0; t < 20; t += 4)
        *(float4*)(ob + t) = make_float4(res[t], res[t + 1], res[t + 2], res[t + 3]);
}

// =============================================================================
extern "C" void kernel_launch(void* const* d_in, const int* in_sizes, int n_in,
                              void* d_out, int out_size)
{
    const float* in = (const float*)d_in[0];
    const float* w1 = (const float*)d_in[1];
    const float* b1 = (const float*)d_in[2];
    const float* w2 = (const float*)d_in[3];
    const float* b2 = (const float*)d_in[4];
    const float* w3 = (const float*)d_in[5];
    const float* b3 = (const float*)d_in[6];
    float* out = (float*)d_out;

    transpose_in<<<4096, 256>>>(in);
    marker0<<<1, 32>>>();                     // shift: k1_fused = launch #4
    marker1<<<1, 32>>>();
    k1_fused<<<dim3(32, 32), 256>>>(w1, b1);
    k2_conv <<<dim3(4, 32, 20), 256>>>(w2, b2);
    k2_scan <<<4096, 256>>>();
    k3_conv <<<dim3(2, 32, 20), 256>>>(w3, b3);
    k3_scan <<<1024, 256>>>(out);
}